// round 1
// baseline (speedup 1.0000x reference)
#include <cuda_runtime.h>

#define NQ  18
#define CHI 16
#define TPB 256

__device__ __forceinline__ float2 cmul(float2 a, float2 b) {
    return make_float2(a.x*b.x - a.y*b.y, a.x*b.y + a.y*b.x);
}
// a * conj(b)
__device__ __forceinline__ float2 cmulc(float2 a, float2 b) {
    return make_float2(a.x*b.x + a.y*b.y, a.y*b.x - a.x*b.y);
}
__device__ __forceinline__ float2 cadd(float2 a, float2 b) {
    return make_float2(a.x + b.x, a.y + b.y);
}

// Shared memory layout (float2 units):
//   bufA   : 18*512   MPS tensors A[j][alpha(16)][s(2)][beta(16)], stride j*512 + a*32 + s*16 + b
//   bufB   : 18*512   ping-pong buffer for MPO application
//   Ush    : 18*4     per-site 2x2 rotation matrices
//   Msc    : 512      contraction scratch
//   Renv   : 256      right environment (16x16)
//   Lenv   : 3*256    left environments L0,L1,L2
//   red    : 256 floats (reduction)
#define F2_COUNT (2*18*512 + 18*4 + 512 + 256 + 3*256)
#define SMEM_BYTES (F2_COUNT*sizeof(float2) + TPB*sizeof(float))

// one transfer step: Renv <- sum_s A_j^s * Renv * A_j^s(dagger)   (all dims 16 here)
__device__ void transfer_R(const float2* Aj, float2* Renv, float2* Msc, int t) {
    // Msc[al][s][bp] = sum_be Aj[al][s][be] * Renv[be][bp]
    for (int i = t; i < 512; i += TPB) {
        int bp = i & 15; int rest = i >> 4; int s = rest & 1; int al = rest >> 1;
        float2 acc = make_float2(0.f, 0.f);
        const float2* arow = Aj + al*32 + s*16;
        for (int be = 0; be < 16; ++be)
            acc = cadd(acc, cmul(arow[be], Renv[be*16 + bp]));
        Msc[al*32 + s*16 + bp] = acc;
    }
    __syncthreads();
    // Renv[a1][a2] = sum_{s,bp} Msc[a1][s][bp] * conj(Aj[a2][s][bp])
    for (int i = t; i < 256; i += TPB) {
        int a1 = i >> 4, a2 = i & 15;
        float2 acc = make_float2(0.f, 0.f);
        for (int s = 0; s < 2; ++s) {
            const float2* mrow = Msc + a1*32 + s*16;
            const float2* arow = Aj + a2*32 + s*16;
            for (int bp = 0; bp < 16; ++bp)
                acc = cadd(acc, cmulc(mrow[bp], arow[bp]));
        }
        Renv[i] = acc;
    }
    __syncthreads();
}

__global__ __launch_bounds__(TPB) void vqc_mps_kernel(
    const float* __restrict__ w, const int* __restrict__ x, float* __restrict__ out)
{
    extern __shared__ float2 sm[];
    float2* bufA = sm;
    float2* bufB = sm + 18*512;
    float2* Ush  = sm + 2*18*512;
    float2* Msc  = Ush + 18*4;
    float2* Renv = Msc + 512;
    float2* Lenv = Renv + 256;              // 3 matrices of 256
    float*  red  = (float*)(Lenv + 3*256);

    const int b = blockIdx.x;
    const int t = threadIdx.x;

    float2* A  = bufA;
    float2* Bb = bufB;

    // ---- init: product state |x_0..x_8, 0..0>, chi=1 ----
    if (t < NQ) {
        int bit = (t < 9) ? x[b*9 + t] : 0;
        A[t*512 + 0]  = make_float2(bit == 0 ? 1.f : 0.f, 0.f);  // [0][0][0]
        A[t*512 + 16] = make_float2(bit == 1 ? 1.f : 0.f, 0.f);  // [0][1][0]
    }
    __syncthreads();

    // ---- 4 layers: rotations (chi=c), then CNOT-staircase MPO (chi: c -> 2c) ----
    for (int l = 0; l < 4; ++l) {
        const int c = 1 << l;

        // rotation matrices for this layer
        if (t < NQ) {
            float phi = w[(l*NQ + t)*3 + 0];
            float th  = w[(l*NQ + t)*3 + 1];
            float om  = w[(l*NQ + t)*3 + 2];
            float sh, ch;  sincosf(0.5f*th, &sh, &ch);
            float sa, ca;  sincosf(-0.5f*(phi + om), &sa, &ca);   // a = e^{-i(phi+om)/2}
            float sb, cb;  sincosf( 0.5f*(phi - om), &sb, &cb);   // b = e^{ i(phi-om)/2}
            Ush[t*4 + 0] = make_float2( ca*ch,  sa*ch);  //  a*c
            Ush[t*4 + 1] = make_float2(-cb*sh, -sb*sh);  // -b*s
            Ush[t*4 + 2] = make_float2( cb*sh, -sb*sh);  //  conj(b)*s
            Ush[t*4 + 3] = make_float2( ca*ch, -sa*ch);  //  conj(a)*c
        }
        __syncthreads();

        // rotations, in place (each thread owns its (alpha,beta) pair)
        for (int j = 0; j < NQ; ++j) {
            int dl = (j == 0)    ? 1 : c;
            int dr = (j == NQ-1) ? 1 : c;
            float2 U00 = Ush[j*4+0], U01 = Ush[j*4+1], U10 = Ush[j*4+2], U11 = Ush[j*4+3];
            int n = dl * dr;
            for (int i = t; i < n; i += TPB) {
                int al = i / dr, be = i % dr;
                float2* p = A + j*512 + al*32 + be;
                float2 v0 = p[0], v1 = p[16];
                p[0]  = cadd(cmul(U00, v0), cmul(U01, v1));
                p[16] = cadd(cmul(U10, v0), cmul(U11, v1));
            }
        }
        __syncthreads();

        // MPO apply: W_j[a,b] = P_b X^a (interior); P_b at site 0; X^a at site 17.
        // out index packing: left (a*c + alpha), right (kb*c + beta)
        for (int j = 0; j < NQ; ++j) {
            int Lo = (j == 0)    ? 1 : 2*c;
            int Ro = (j == NQ-1) ? 1 : 2*c;
            int n = Lo * 2 * Ro;
            for (int i = t; i < n; i += TPB) {
                int bp   = i % Ro;
                int rest = i / Ro;
                int s    = rest & 1;
                int ap   = rest >> 1;
                int a  = (j == 0)    ? 0 : (ap / c);
                int al = (j == 0)    ? 0 : (ap % c);
                int kb = (j == NQ-1) ? -1 : (bp / c);
                int be = (j == NQ-1) ? 0  : (bp % c);
                float2 v;
                if (j < NQ-1 && s != kb) v = make_float2(0.f, 0.f);
                else                     v = A[j*512 + al*32 + (s ^ a)*16 + be];
                Bb[j*512 + ap*32 + s*16 + bp] = v;
            }
        }
        __syncthreads();
        float2* tmp = A; A = Bb; Bb = tmp;
    }

    // ---- contraction: chi = 16 everywhere (site0 left=1, site17 right=1) ----

    // Renv from site 17: R[a1][a2] = sum_s A17[a1][s][0] conj(A17[a2][s][0])
    for (int i = t; i < 256; i += TPB) {
        int a1 = i >> 4, a2 = i & 15;
        float2 acc = make_float2(0.f, 0.f);
        for (int s = 0; s < 2; ++s)
            acc = cadd(acc, cmulc(A[17*512 + a1*32 + s*16], A[17*512 + a2*32 + s*16]));
        Renv[i] = acc;
    }
    __syncthreads();

    for (int j = 16; j >= 4; --j) transfer_R(A + j*512, Renv, Msc, t);

    // left environments L0,L1,L2 (ket index first)
    for (int i = t; i < 256; i += TPB) {
        int b1 = i >> 4, b2 = i & 15;
        float2 acc = make_float2(0.f, 0.f);
        for (int s = 0; s < 2; ++s)
            acc = cadd(acc, cmulc(A[0*512 + s*16 + b1], A[0*512 + s*16 + b2]));
        Lenv[i] = acc;
    }
    __syncthreads();
    for (int m = 1; m <= 2; ++m) {
        float2* Lp = Lenv + (m-1)*256;
        float2* Ln = Lenv + m*256;
        // Msc[b2][s][g] = sum_b1 Lp[b1][b2] * A_m[b1][s][g]
        for (int i = t; i < 512; i += TPB) {
            int g = i & 15; int rest = i >> 4; int s = rest & 1; int b2 = rest >> 1;
            float2 acc = make_float2(0.f, 0.f);
            for (int b1 = 0; b1 < 16; ++b1)
                acc = cadd(acc, cmul(Lp[b1*16 + b2], A[m*512 + b1*32 + s*16 + g]));
            Msc[b2*32 + s*16 + g] = acc;
        }
        __syncthreads();
        // Ln[g1][g2] = sum_{b2,s} Msc[b2][s][g1] * conj(A_m[b2][s][g2])
        for (int i = t; i < 256; i += TPB) {
            int g1 = i >> 4, g2 = i & 15;
            float2 acc = make_float2(0.f, 0.f);
            for (int b2 = 0; b2 < 16; ++b2)
                for (int s = 0; s < 2; ++s)
                    acc = cadd(acc, cmulc(Msc[b2*32 + s*16 + g1], A[m*512 + b2*32 + s*16 + g2]));
            Ln[i] = acc;
        }
        __syncthreads();
    }

    // EVs for q = 3..0 : t_s = L_{q-1} . (A_q^s x conj(A_q^s)) . R_{q+1};  EV = (t0-t1)/(t0+t1)
    for (int q = 3; q >= 0; --q) {
        const int dl = (q == 0) ? 1 : 16;
        const float2* Lp = (q == 0) ? nullptr : (Lenv + (q-1)*256);
        float tv[2];
        for (int s = 0; s < 2; ++s) {
            // X[al][bp] = sum_be A_q[al][s][be] * Renv[be][bp]   -> Msc (dl x 16)
            for (int i = t; i < dl*16; i += TPB) {
                int bp = i & 15, al = i >> 4;
                float2 acc = make_float2(0.f, 0.f);
                const float2* arow = A + q*512 + al*32 + s*16;
                for (int be = 0; be < 16; ++be)
                    acc = cadd(acc, cmul(arow[be], Renv[be*16 + bp]));
                Msc[al*16 + bp] = acc;
            }
            __syncthreads();
            float part = 0.f;
            for (int i = t; i < dl*16; i += TPB) {
                int bp = i & 15, a2 = i >> 4;
                float2 z;
                if (q == 0) z = Msc[bp];
                else {
                    z = make_float2(0.f, 0.f);
                    for (int al = 0; al < 16; ++al)
                        z = cadd(z, cmul(Lp[al*16 + a2], Msc[al*16 + bp]));
                }
                float2 aa = A[q*512 + a2*32 + s*16 + bp];
                part += z.x*aa.x + z.y*aa.y;   // Re(z * conj(aa))
            }
            red[t] = part;
            __syncthreads();
            for (int off = TPB/2; off > 0; off >>= 1) {
                if (t < off) red[t] += red[t + off];
                __syncthreads();
            }
            tv[s] = red[0];
            __syncthreads();
        }
        if (t == 0) out[b*4 + q] = (tv[0] - tv[1]) / (tv[0] + tv[1]);
        if (q > 0) transfer_R(A + q*512, Renv, Msc, t);
    }
}

extern "C" void kernel_launch(void* const* d_in, const int* in_sizes, int n_in,
                              void* d_out, int out_size) {
    const float* w;
    const int*   xin;
    if (n_in >= 2 && in_sizes[0] == 4*18*3) {
        w   = (const float*)d_in[0];
        xin = (const int*)  d_in[1];
    } else {
        w   = (const float*)d_in[1];
        xin = (const int*)  d_in[0];
    }
    float* out = (float*)d_out;

    cudaFuncSetAttribute(vqc_mps_kernel,
                         cudaFuncAttributeMaxDynamicSharedMemorySize,
                         (int)SMEM_BYTES);
    vqc_mps_kernel<<<64, TPB, SMEM_BYTES>>>(w, xin, out);
}

// round 2
// speedup vs baseline: 1.9713x; 1.9713x over previous
#include <cuda_runtime.h>

#define TPB  256
#define ST   17            // padded row stride (float2 units) for site tensors / Msct
#define SITE (32*ST)       // 544 float2 per site tensor

__device__ __forceinline__ void cmac(float2& acc, float2 a, float2 b) {        // acc += a*b
    acc.x = fmaf(a.x, b.x, fmaf(-a.y, b.y, acc.x));
    acc.y = fmaf(a.x, b.y, fmaf( a.y, b.x, acc.y));
}
__device__ __forceinline__ void cmacc(float2& acc, float2 a, float2 b) {       // acc += a*conj(b)
    acc.x = fmaf(a.x, b.x, fmaf( a.y, b.y, acc.x));
    acc.y = fmaf(a.y, b.x, fmaf(-a.x, b.y, acc.y));
}

// smem: bufA 18*544 | bufB 18*544 | Ush 72 | Msct 544 | Msc 512 | Renv 256 | Lenv 768 | red 64f
#define F2_TOTAL (2*18*SITE + 72 + SITE + 512 + 256 + 768)
#define SMEM_BYTES (F2_TOTAL*8 + 64*4)

// Renv <- sum_s A_j^s . Renv . A_j^s(dagger), chi=16. Two conflict-free NN GEMMs.
__device__ __forceinline__ void transfer(const float2* __restrict__ Aj,
                                         float2* __restrict__ Renv,
                                         float2* __restrict__ Msct, int t)
{
    // phase 1: Msc = A (32x16) . Renv (16x16); write conj-transposed, stride 17
    {
        const int r = t >> 4, bp = t & 15;
        const float2* row0 = Aj + r*ST;
        const float2* row1 = Aj + (r+16)*ST;
        float2 acc0 = make_float2(0.f,0.f), acc1 = make_float2(0.f,0.f);
#pragma unroll
        for (int be = 0; be < 16; ++be) {
            float2 rv = Renv[be*16 + bp];
            cmac(acc0, row0[be], rv);
            cmac(acc1, row1[be], rv);
        }
        const int s = r & 1, al = r >> 1;
        const int k = s*16 + bp;
        Msct[k*ST + al    ] = make_float2(acc0.x, -acc0.y);
        Msct[k*ST + al + 8] = make_float2(acc1.x, -acc1.y);
    }
    __syncthreads();
    // phase 2: P[a2][a1] = sum_k A2[a2][k] * Msct[k][a1];  Renv[a1][a2] = conj(P)
    {
        const int a1 = t >> 4, a2 = t & 15;
        float2 P = make_float2(0.f,0.f);
#pragma unroll
        for (int kk = 0; kk < 32; ++kk) {
            float2 av = Aj[(a2*2 + (kk>>4))*ST + (kk & 15)];
            float2 mv = Msct[kk*ST + a1];
            cmac(P, av, mv);
        }
        Renv[a1*16 + a2] = make_float2(P.x, -P.y);
    }
    __syncthreads();
}

__global__ void __launch_bounds__(TPB, 1) vqc_mps_kernel(
    const float* __restrict__ w, const int* __restrict__ x, float* __restrict__ out)
{
    extern __shared__ float2 sm[];
    float2* bufA = sm;
    float2* bufB = bufA + 18*SITE;
    float2* Ush  = bufB + 18*SITE;
    float2* Msct = Ush + 72;
    float2* Msc  = Msct + SITE;
    float2* Renv = Msc + 512;
    float2* Lenv = Renv + 256;
    float*  red  = (float*)(Lenv + 768);

    const int b = blockIdx.x, t = threadIdx.x;
    const int lane = t & 31, wid = t >> 5;

    // zero both MPS buffers (unused slots must be 0: edge-site junk safety)
    {
        float4* z4 = (float4*)sm;
        for (int i = t; i < (2*18*SITE)/2; i += TPB) z4[i] = make_float4(0.f,0.f,0.f,0.f);
    }
    __syncthreads();

    // product state |x_0..x_8, 0..0>
    if (t < 18) {
        int bit = (t < 9) ? x[b*9 + t] : 0;
        bufA[t*SITE + 0 ] = make_float2(bit == 0 ? 1.f : 0.f, 0.f);   // (al=0,s=0,be=0)
        bufA[t*SITE + ST] = make_float2(bit == 1 ? 1.f : 0.f, 0.f);   // (al=0,s=1,be=0)
    }
    __syncthreads();

    float2* A  = bufA;
    float2* Bb = bufB;

    // ---- 4 layers: fused (rotation + CNOT-staircase MPO), chi: c -> 2c ----
    for (int l = 0; l < 4; ++l) {
        const int c2 = 2 << l;          // output bond dim
        const int cm = (1 << l) - 1;    // input bond mask

        if (t < 18) {
            float phi = w[(l*18 + t)*3 + 0];
            float th  = w[(l*18 + t)*3 + 1];
            float om  = w[(l*18 + t)*3 + 2];
            float sh, ch; sincosf(0.5f*th, &sh, &ch);
            float sa, ca; sincosf(-0.5f*(phi + om), &sa, &ca);
            float sb, cb; sincosf( 0.5f*(phi - om), &sb, &cb);
            Ush[t*4+0] = make_float2( ca*ch,  sa*ch);   // U[0][0] = a*cos
            Ush[t*4+1] = make_float2(-cb*sh, -sb*sh);   // U[0][1] = -b*sin
            Ush[t*4+2] = make_float2( cb*sh, -sb*sh);   // U[1][0] = conj(b)*sin
            Ush[t*4+3] = make_float2( ca*ch, -sa*ch);   // U[1][1] = conj(a)*cos
        }
        __syncthreads();

        for (int j = 0; j < 18; ++j) {
            const int Lo = (j == 0)  ? 1 : c2;
            const int Ro = (j == 17) ? 1 : c2;
            const int n  = Lo * 2 * Ro;
            const float2* Aj = A  + j*SITE;
            float2*       Bj = Bb + j*SITE;
            const float2 U00 = Ush[j*4+0], U01 = Ush[j*4+1];
            const float2 U10 = Ush[j*4+2], U11 = Ush[j*4+3];
            for (int i = t; i < n; i += TPB) {
                int bp, rest;
                if (j == 17) { bp = 0;           rest = i; }
                else         { bp = i & (c2-1);  rest = i >> (l+1); }
                const int s  = rest & 1;
                const int ap = rest >> 1;
                const int a  = (j == 0)  ? 0 : (ap >> l);
                const int al = (j == 0)  ? 0 : (ap & cm);
                const int kb = (j == 17) ? s : (bp >> l);
                const int be = (j == 17) ? 0 : (bp & cm);
                float2 v = make_float2(0.f, 0.f);
                if (kb == s) {
                    const int u = s ^ a;
                    float2 A0 = Aj[al*(2*ST) + be];
                    float2 A1 = Aj[al*(2*ST) + ST + be];
                    float2 Ua = (u == 0) ? U00 : U10;
                    float2 Ub = (u == 0) ? U01 : U11;
                    cmac(v, Ua, A0);
                    cmac(v, Ub, A1);
                }
                Bj[(ap*2 + s)*ST + bp] = v;
            }
        }
        __syncthreads();
        float2* tmp = A; A = Bb; Bb = tmp;
    }

    // ---- contraction, chi=16 everywhere ----

    // Renv init from site 17 (right dim 1)
    {
        const int a1 = t >> 4, a2 = t & 15;
        const float2* A17 = A + 17*SITE;
        float2 acc = make_float2(0.f,0.f);
        cmacc(acc, A17[(a1*2  )*ST], A17[(a2*2  )*ST]);
        cmacc(acc, A17[(a1*2+1)*ST], A17[(a2*2+1)*ST]);
        Renv[a1*16 + a2] = acc;
    }
    __syncthreads();

    for (int j = 16; j >= 4; --j) transfer(A + j*SITE, Renv, Msct, t);

    // left environments L0,L1,L2
    {
        const int b1 = t >> 4, b2 = t & 15;
        const float2* A0 = A;     // site 0, rows (al=0,s)
        float2 acc = make_float2(0.f,0.f);
        cmacc(acc, A0[b1],      A0[b2]);
        cmacc(acc, A0[ST + b1], A0[ST + b2]);
        Lenv[t] = acc;
    }
    __syncthreads();
    for (int m = 1; m <= 2; ++m) {
        const float2* Lp = Lenv + (m-1)*256;
        float2*       Ln = Lenv + m*256;
        const float2* Am = A + m*SITE;
        // Msc[b2][s][g] = sum_b1 Lp[b1][b2] * Am[(b1,s)][g]   (512 outs, 2/thread)
        {
            const int g = t & 15, s = (t >> 4) & 1, b2a = t >> 5;  // b2a 0..7
            float2 acc0 = make_float2(0.f,0.f), acc1 = make_float2(0.f,0.f);
#pragma unroll
            for (int b1 = 0; b1 < 16; ++b1) {
                float2 av = Am[(b1*2 + s)*ST + g];
                cmac(acc0, Lp[b1*16 + b2a    ], av);
                cmac(acc1, Lp[b1*16 + b2a + 8], av);
            }
            Msc[ b2a     *32 + s*16 + g] = acc0;
            Msc[(b2a + 8)*32 + s*16 + g] = acc1;
        }
        __syncthreads();
        // Ln[g1][g2] = sum_{b2,s} Msc[b2][s][g1] * conj(Am[(b2,s)][g2])
        {
            const int g1 = t >> 4, g2 = t & 15;
            float2 acc = make_float2(0.f,0.f);
#pragma unroll
            for (int kk = 0; kk < 32; ++kk)
                cmacc(acc, Msc[(kk>>1)*32 + (kk&1)*16 + g1], Am[kk*ST + g2]);
            Ln[t] = acc;
        }
        __syncthreads();
    }

    // ---- EVs q=3..0 ----
    for (int q = 3; q >= 0; --q) {
        const float2* Aq = A + q*SITE;

        // phase A: X[(al,s)][bp] = sum_be Aq[(al,s)][be] * Renv[be][bp]  (both spins)
        {
            const int r = t >> 4, bp = t & 15;
            const float2* row0 = Aq + r*ST;
            const float2* row1 = Aq + (r+16)*ST;
            float2 acc0 = make_float2(0.f,0.f), acc1 = make_float2(0.f,0.f);
#pragma unroll
            for (int be = 0; be < 16; ++be) {
                float2 rv = Renv[be*16 + bp];
                cmac(acc0, row0[be], rv);
                cmac(acc1, row1[be], rv);
            }
            Msc[ r     *16 + bp] = acc0;
            Msc[(r+16) *16 + bp] = acc1;
        }
        __syncthreads();

        // phase B: signed contributions + two-level reduction
        float num = 0.f, den = 0.f;
        if (q == 0) {
            if (t < 32) {
                const int s = t >> 4, bp = t & 15;
                float2 z  = Msc[s*16 + bp];          // row (al=0,s)
                float2 av = Aq[s*ST + bp];
                float v = z.x*av.x + z.y*av.y;       // Re(z * conj(av))
                num = s ? -v : v;  den = v;
            }
        } else {
            const float2* Lp = Lenv + (q-1)*256;
            const int bp = t & 15, s = (t >> 4) & 1, a2a = t >> 5;  // a2a 0..7
#pragma unroll
            for (int h = 0; h < 2; ++h) {
                const int a2 = a2a + h*8;
                float2 z = make_float2(0.f,0.f);
#pragma unroll
                for (int al = 0; al < 16; ++al)
                    cmac(z, Lp[al*16 + a2], Msc[(al*2 + s)*16 + bp]);
                float2 av = Aq[(a2*2 + s)*ST + bp];
                float v = z.x*av.x + z.y*av.y;
                num += s ? -v : v;  den += v;
            }
        }
#pragma unroll
        for (int o = 16; o > 0; o >>= 1) {
            num += __shfl_xor_sync(0xffffffffu, num, o);
            den += __shfl_xor_sync(0xffffffffu, den, o);
        }
        if (lane == 0) { red[wid*2] = num; red[wid*2+1] = den; }
        __syncthreads();
        if (t == 0) {
            float N = 0.f, D = 0.f;
#pragma unroll
            for (int wdx = 0; wdx < 8; ++wdx) { N += red[wdx*2]; D += red[wdx*2+1]; }
            out[b*4 + q] = N / D;
        }
        if (q > 0) transfer(Aq, Renv, Msct, t);
    }
}

extern "C" void kernel_launch(void* const* d_in, const int* in_sizes, int n_in,
                              void* d_out, int out_size) {
    const float* w;
    const int*   xin;
    if (n_in >= 2 && in_sizes[0] == 4*18*3) {
        w   = (const float*)d_in[0];
        xin = (const int*)  d_in[1];
    } else {
        w   = (const float*)d_in[1];
        xin = (const int*)  d_in[0];
    }
    float* out = (float*)d_out;

    cudaFuncSetAttribute(vqc_mps_kernel,
                         cudaFuncAttributeMaxDynamicSharedMemorySize,
                         (int)SMEM_BYTES);
    vqc_mps_kernel<<<64, TPB, SMEM_BYTES>>>(w, xin, out);
}